// round 9
// baseline (speedup 1.0000x reference)
#include <cuda_runtime.h>

// DILATE loss — band-wavefront soft-DTW fwd+bwd, TWO batches per CTA (grid 128,
// one CTA per SM). Each warp carries two independent DP chains (one per batch)
// that interleave in the instruction stream to hide the serial-recurrence latency
// (shfl/LDS -> min-net -> ex2 -> lg2). All per-batch state in [2] arrays indexed
// only by fully-unrolled loops; backward R-ring statically indexed (no local mem).

#define NB    256
#define NN    336
#define NV    7
#define ND    673
#define DS    352
#define TPB   352
#define NW    11
#define W2    448            // boundary array width (j in [-30, 398] + pad 32)
#define PADB  32             // boundary front pad
#define PADO  32             // point front pad
#define PSTR  12             // floats per packed point (2 x float4 used)
#define NPTS  432            // padded point count (covers j-1+PADO up to 429)
#define LOG2E 1.4426950408889634f
#define LN2   0.6931471805599453f
#define BIG2  1.442695e8f
#define NEGS  -1.0e30f
#define PF    8
#define FULLM 0xffffffffu

// g_R padded 32 diagonals front and 64 back (unguarded out-of-window reads land in pads)
__device__ float    g_R[((size_t)NB * ND + 96) * DS];
__device__ double   g_shape_acc;
__device__ double   g_temp_acc;
__device__ unsigned g_done;

static __device__ __forceinline__ float ex2f(float x) {
    float r; asm("ex2.approx.f32 %0, %1;" : "=f"(r) : "f"(x)); return r;
}
static __device__ __forceinline__ float lg2f(float x) {
    float r; asm("lg2.approx.f32 %0, %1;" : "=f"(r) : "f"(x)); return r;
}

extern __shared__ float smem[];

__global__ __launch_bounds__(TPB, 1)
void dilate_kernel(const float* __restrict__ outputs,
                   const float* __restrict__ targets,
                   float* __restrict__ out) {
    const int tid = threadIdx.x;
    const int w   = tid >> 5;
    const int l   = tid & 31;
    const int i   = 32 * w + l + 1;
    const bool row_ok = (i <= NN);

    // smem layout (floats): opack[2][NPTS][PSTR], bndA[2][NW][W2], bndB[2][NW][W2]
    float* opack0 = smem;
    float* opack1 = opack0 + NPTS * PSTR;
    float* bndA0  = opack1 + NPTS * PSTR;
    float* bndA1  = bndA0 + NW * W2;
    float* bndB0  = bndA1 + NW * W2;
    float* bndB1  = bndB0 + NW * W2;
    float* opackU[2] = {opack0, opack1};
    float* bndAU[2]  = {bndA0, bndA1};
    float* bndBU[2]  = {bndB0, bndB1};
    __shared__ float warpsum[NW];
    __shared__ float shape_s[2];

    float* gRb[2];
#pragma unroll
    for (int u = 0; u < 2; u++) {
        int b = 2 * blockIdx.x + u;
        gRb[u] = g_R + 32 * (size_t)DS + (size_t)b * ND * DS;
    }

    // load + pack points for both batches
#pragma unroll
    for (int u = 0; u < 2; u++) {
        float* op = opackU[u];
        for (int k = tid; k < NPTS * PSTR; k += TPB) op[k] = 0.f;
    }
    __syncthreads();
#pragma unroll
    for (int u = 0; u < 2; u++) {
        const float* ob = outputs + (size_t)(2 * blockIdx.x + u) * NN * NV;
        float* op = opackU[u];
        for (int k = tid; k < NN * NV; k += TPB) {
            int j = k / NV, v = k - j * NV;
            op[(j + PADO) * PSTR + v] = ob[k];
        }
    }
    __syncthreads();
#pragma unroll
    for (int u = 0; u < 2; u++) {
        float* op = opackU[u];
        for (int j = tid; j < NN; j += TPB) {
            float s = 0.f;
#pragma unroll
            for (int v = 0; v < NV; v++) { float x = op[(j + PADO) * PSTR + v]; s = fmaf(x, x, s); }
            op[(j + PADO) * PSTR + 7] = s * LOG2E;
        }
    }
    float tL[2][NV], tn2[2];
#pragma unroll
    for (int u = 0; u < 2; u++) {
        tn2[u] = 0.f;
        if (row_ok) {
            const float* tb = targets + (size_t)(2 * blockIdx.x + u) * NN * NV;
            float tnr = 0.f;
#pragma unroll
            for (int v = 0; v < NV; v++) {
                float tv = tb[(i - 1) * NV + v];
                tnr = fmaf(tv, tv, tnr);
                tL[u][v] = 2.f * LOG2E * tv;
            }
            tn2[u] = tnr * LOG2E;
        } else {
#pragma unroll
            for (int v = 0; v < NV; v++) tL[u][v] = 0.f;
        }
    }
    // forward boundary prefill: BIG2 everywhere except R[0][0] = 0 (race-free fill)
#pragma unroll
    for (int u = 0; u < 2; u++) {
        float* bA = bndAU[u];
        for (int k = tid; k < NW * W2; k += TPB) bA[k] = (k == PADB) ? 0.f : BIG2;
    }
    if (tid < 2) shape_s[tid] = 0.f;
    __syncthreads();

    // ================= forward =================
    {
        float Rprev[2] = {BIG2, BIG2}, upc[2] = {BIG2, BIG2},
              upp[2]  = {BIG2, BIG2}, prevB[2] = {BIG2, BIG2};
        const int off = 64 * w;
        const int pstart = off >> 5, pend = (off + 366) >> 5;
        const float* bArow[2] = {bndA0 + w * W2 + PADB, bndA1 + w * W2 + PADB};
        float* bAnext[2] = {bndA0 + (w + 1) * W2 + PADB, bndA1 + (w + 1) * W2 + PADB};
        for (int p = 0; p < 31; p++) {
            if (p >= pstart && p <= pend) {
                int s0 = p << 5;
                int j = s0 - off - l + 1;
                if (p == pstart && l == 0) {
#pragma unroll
                    for (int u = 0; u < 2; u++) prevB[u] = bArow[u][0];
                }
                float* gptr[2] = {gRb[0] + (size_t)(s0 - 32 * w + 2) * DS + i,
                                  gRb[1] + (size_t)(s0 - 32 * w + 2) * DS + i};
                const float* oj[2] = {opack0 + (j - 1 + PADO) * PSTR,
                                      opack1 + (j - 1 + PADO) * PSTR};
#pragma unroll 4
                for (int k = 0; k < 32; k++) {
                    bool act = row_ok && ((unsigned)(j - 1) < (unsigned)NN);
#pragma unroll
                    for (int u = 0; u < 2; u++) {
                        const float4 a = *(const float4*)(oj[u]);
                        const float4 c = *(const float4*)(oj[u] + 4);
                        float acc0 = tn2[u] + c.w;
                        acc0 = fmaf(-tL[u][0], a.x, acc0);
                        acc0 = fmaf(-tL[u][1], a.y, acc0);
                        acc0 = fmaf(-tL[u][2], a.z, acc0);
                        acc0 = fmaf(-tL[u][3], a.w, acc0);
                        acc0 = fmaf(-tL[u][4], c.x, acc0);
                        acc0 = fmaf(-tL[u][5], c.y, acc0);
                        acc0 = fmaf(-tL[u][6], c.z, acc0);
                        float D2 = fmaxf(acc0, 0.f);
                        float ru = upc[u], rd = upp[u], curB = 0.f;
                        if (l == 0) { curB = bArow[u][j]; ru = curB; rd = prevB[u]; }
                        float rl = Rprev[u];
                        float lo = fminf(rd, ru), hi = fmaxf(rd, ru);
                        float m  = fminf(lo, rl);
                        float md = fmaxf(lo, fminf(hi, rl));
                        float Mx = fmaxf(hi, rl);
                        float z  = 1.f + ex2f(m - md) + ex2f(m - Mx);
                        float Rn = D2 + m - lg2f(z);
                        Rn = act ? Rn : BIG2;
                        if (act) {
                            *gptr[u] = Rn;
                            if (l == 31 && w < NW - 1) bAnext[u][j] = Rn;
                        }
                        float sh = __shfl_up_sync(FULLM, Rn, 1);
                        upp[u] = upc[u]; upc[u] = sh;
                        if (l == 0) prevB[u] = curB;
                        Rprev[u] = Rn;
                        gptr[u] += DS; oj[u] += PSTR;
                    }
                    j++;
                }
            }
            __syncthreads();
        }
    }

    // re-init boundaries for backward: E = 0, s = NEGS
#pragma unroll
    for (int u = 0; u < 2; u++) {
        float* bA = bndAU[u];
        float* bB = bndBU[u];
        for (int k = tid; k < NW * W2; k += TPB) { bA[k] = 0.f; bB[k] = NEGS; }
    }
    __syncthreads();

    // ================= backward =================
    float tacc = 0.f;
    {
        float Eprev[2] = {0.f, 0.f}, Sprev[2] = {NEGS, NEGS};
        float Edn1[2]  = {0.f, 0.f}, Sdn1[2]  = {NEGS, NEGS};
        float Edn2[2]  = {0.f, 0.f}, Sdn2[2]  = {NEGS, NEGS};
        float rring[2][PF];
        const int off = 64 * (10 - w);
        const int pstart = off >> 5, pend = (off + 366) >> 5;
        const float* bArow[2] = {bndA0 + w * W2 + PADB, bndA1 + w * W2 + PADB};
        const float* bBrow[2] = {bndB0 + w * W2 + PADB, bndB1 + w * W2 + PADB};
        float* bAprev[2] = {bndA0 + (w - 1) * W2 + PADB, bndA1 + (w - 1) * W2 + PADB};
        float* bBprev[2] = {bndB0 + (w - 1) * W2 + PADB, bndB1 + (w - 1) * W2 + PADB};
        const bool seed_lane = (i == NN);
        for (int p = 0; p < 32; p++) {
            if (p >= pstart && p <= pend) {
                int s0 = p << 5;
                if (p == pstart) {
#pragma unroll
                    for (int q = 0; q < PF; q++) {
#pragma unroll
                        for (int u = 0; u < 2; u++)
                            rring[u][q] = gRb[u][(size_t)(1008 - 32 * w - s0 - q) * DS + i];
                    }
                }
                int j = 367 + off - s0 - l;
                float df = (float)(i - j);
                const float* ppf[2] = {gRb[0] + (size_t)(1008 - 32 * w - s0 - PF) * DS + i,
                                       gRb[1] + (size_t)(1008 - 32 * w - s0 - PF) * DS + i};
                const float* oj[2] = {opack0 + (j - 1 + PADO) * PSTR,
                                      opack1 + (j - 1 + PADO) * PSTR};
#pragma unroll
                for (int kb = 0; kb < 32 / PF; kb++) {
#pragma unroll
                    for (int kk = 0; kk < PF; kk++) {
                        bool act = row_ok && ((unsigned)(j - 1) < (unsigned)NN);
#pragma unroll
                        for (int u = 0; u < 2; u++) {
                            float Rij = rring[u][kk];
                            rring[u][kk] = *ppf[u]; ppf[u] -= DS;
                            if (l == 31) { Edn1[u] = bArow[u][j]; Sdn1[u] = bBrow[u][j]; }
                            const float4 a = *(const float4*)(oj[u]);
                            const float4 c = *(const float4*)(oj[u] + 4);
                            float acc0 = tn2[u] + c.w;
                            acc0 = fmaf(-tL[u][0], a.x, acc0);
                            acc0 = fmaf(-tL[u][1], a.y, acc0);
                            acc0 = fmaf(-tL[u][2], a.z, acc0);
                            acc0 = fmaf(-tL[u][3], a.w, acc0);
                            acc0 = fmaf(-tL[u][4], c.x, acc0);
                            acc0 = fmaf(-tL[u][5], c.y, acc0);
                            acc0 = fmaf(-tL[u][6], c.z, acc0);
                            float D2 = fmaxf(acc0, 0.f);
                            float w1 = ex2f(Sdn1[u] - Rij);
                            float w2 = ex2f(Sprev[u] - Rij);
                            float w3 = ex2f(Sdn2[u] - Rij);
                            float En = fmaf(Edn1[u], w1, fmaf(Eprev[u], w2, Edn2[u] * w3));
                            if (seed_lane && j == NN) { En = 1.f; shape_s[u] = Rij * LN2; }
                            float Sn = Rij - D2;
                            En = act ? En : 0.f;
                            Sn = act ? Sn : NEGS;
                            tacc = fmaf(En, df * df, tacc);
                            if (act && l == 0 && w > 0) { bAprev[u][j] = En; bBprev[u][j] = Sn; }
                            float Es = __shfl_down_sync(FULLM, En, 1);
                            float Ss = __shfl_down_sync(FULLM, Sn, 1);
                            Edn2[u] = Edn1[u]; Sdn2[u] = Sdn1[u];
                            Edn1[u] = Es;      Sdn1[u] = Ss;
                            Eprev[u] = En;     Sprev[u] = Sn;
                            oj[u] -= PSTR;
                        }
                        j--; df += 1.f;
                    }
                }
            }
            __syncthreads();
        }
    }

    // ------- reduce temporal accumulator, finalize in last CTA -------
#pragma unroll
    for (int o2 = 16; o2; o2 >>= 1) tacc += __shfl_down_sync(FULLM, tacc, o2);
    if (l == 0) warpsum[w] = tacc;
    __syncthreads();
    if (tid == 0) {
        float sum = 0.f;
#pragma unroll
        for (int q = 0; q < NW; q++) sum += warpsum[q];
        atomicAdd(&g_temp_acc, (double)sum);
        atomicAdd(&g_shape_acc, (double)shape_s[0] + (double)shape_s[1]);
        __threadfence();
        unsigned old = atomicAdd(&g_done, 1u);
        if (old == (NB / 2) - 1) {
            __threadfence();
            double shape    = g_shape_acc / (double)NB;
            double temporal = g_temp_acc / ((double)NN * NN * NB * NB);
            out[0] = (float)(0.5 * shape + 0.5 * temporal);
            g_shape_acc = 0.0;
            g_temp_acc  = 0.0;
            __threadfence();
            g_done = 0u;
        }
    }
}

extern "C" void kernel_launch(void* const* d_in, const int* in_sizes, int n_in,
                              void* d_out, int out_size) {
    const float* outputs = (const float*)d_in[0];
    const float* targets = (const float*)d_in[1];
    static int smem_set = 0;
    int smem_bytes = (2 * NPTS * PSTR + 4 * NW * W2) * sizeof(float);   // 120320 B
    if (!smem_set) {
        cudaFuncSetAttribute(dilate_kernel, cudaFuncAttributeMaxDynamicSharedMemorySize,
                             smem_bytes);
        smem_set = 1;
    }
    dilate_kernel<<<NB / 2, TPB, smem_bytes>>>(outputs, targets, (float*)d_out);
}

// round 10
// speedup vs baseline: 1.6746x; 1.6746x over previous
#include <cuda_runtime.h>

// DILATE loss — band-wavefront soft-DTW fwd+bwd, 2 ROWS PER LANE.
// Warp w owns rows 64w+1..64w+64 (lane l: rows i0=64w+2l+1, i1=i0+1).
// At each step a warp processes one full anti-diagonal slice: cell A=(i0,jA),
// cell B=(i1,jA-1) — independent chains, deps all from previous steps (lane-local
// regs + one shfl of the neighbor row). Warp skew 96 columns, barrier per 32 steps.
// Base-2 math; R stored diagonal-major (d*DS + i-1), backward reads float2/lane
// via an 8-deep statically-indexed prefetch ring.

#define NB    256
#define NN    336
#define NV    7
#define ND    673
#define DS    352
#define TPB   192
#define NWARP 6
#define NBND  7
#define W2    576
#define PADB  96
#define PADO  96
#define PSTR  12
#define NPTS  528
#define LOG2E 1.4426950408889634f
#define LN2   0.6931471805599453f
#define BIG2  1.442695e8f
#define NEGS  -1.0e30f
#define PF    8
#define FULLM 0xffffffffu

// 32 diagonals front pad + 128 back pad (unguarded out-of-window reads land in pads)
__device__ float    g_R[((size_t)NB * ND + 160) * DS];
__device__ double   g_shape_acc;
__device__ double   g_temp_acc;
__device__ unsigned g_done;

static __device__ __forceinline__ float ex2f(float x) {
    float r; asm("ex2.approx.f32 %0, %1;" : "=f"(r) : "f"(x)); return r;
}
static __device__ __forceinline__ float lg2f(float x) {
    float r; asm("lg2.approx.f32 %0, %1;" : "=f"(r) : "f"(x)); return r;
}
// softmin in base-2: m - lg2(1 + 2^(m-md) + 2^(m-Mx))
static __device__ __forceinline__ float softmin2(float rd, float ru, float rl) {
    float lo = fminf(rd, ru), hi = fmaxf(rd, ru);
    float m  = fminf(lo, rl);
    float md = fmaxf(lo, fminf(hi, rl));
    float Mx = fmaxf(hi, rl);
    float z  = 1.f + ex2f(m - md) + ex2f(m - Mx);
    return m - lg2f(z);
}

extern __shared__ float smem[];

__global__ __launch_bounds__(TPB, 2)
void dilate_kernel(const float* __restrict__ outputs,
                   const float* __restrict__ targets,
                   float* __restrict__ out) {
    const int b   = blockIdx.x;
    const int tid = threadIdx.x;
    const int w   = tid >> 5;
    const int l   = tid & 31;
    const int i0  = 64 * w + 2 * l + 1;
    const int i1  = i0 + 1;
    const bool ok0 = (i0 <= NN), ok1 = (i1 <= NN);

    float* opack = smem;                    // [NPTS][PSTR]: col j at slot j-1+PADO
    float* bnd1  = opack + NPTS * PSTR;     // fwd: R boundary rows; bwd: E rows [NBND][W2]
    float* bnd2  = bnd1 + NBND * W2;        // bwd: s rows
    __shared__ float warpsum[NWARP];
    __shared__ float shape_s;

    const float* ob = outputs + (size_t)b * NN * NV;
    const float* tb = targets + (size_t)b * NN * NV;

    // ---- pack output points (zero-padded) ----
    for (int k = tid; k < NPTS * PSTR; k += TPB) opack[k] = 0.f;
    __syncthreads();
    for (int k = tid; k < NN * NV; k += TPB) {
        int j = k / NV, v = k - j * NV;
        opack[(j + PADO) * PSTR + v] = ob[k];   // column j+1 at slot j+PADO
    }
    __syncthreads();
    for (int j = tid; j < NN; j += TPB) {
        float s = 0.f;
#pragma unroll
        for (int v = 0; v < NV; v++) { float x = opack[(j + PADO) * PSTR + v]; s = fmaf(x, x, s); }
        opack[(j + PADO) * PSTR + 7] = s * LOG2E;
    }
    // ---- per-lane target rows (two rows) ----
    float tL0[NV], tL1[NV], tn20 = 0.f, tn21 = 0.f;
    if (ok0) {
        float tnr = 0.f;
#pragma unroll
        for (int v = 0; v < NV; v++) {
            float tv = tb[(i0 - 1) * NV + v];
            tnr = fmaf(tv, tv, tnr);
            tL0[v] = 2.f * LOG2E * tv;
        }
        tn20 = tnr * LOG2E;
    } else {
#pragma unroll
        for (int v = 0; v < NV; v++) tL0[v] = 0.f;
    }
    if (ok1) {
        float tnr = 0.f;
#pragma unroll
        for (int v = 0; v < NV; v++) {
            float tv = tb[(i1 - 1) * NV + v];
            tnr = fmaf(tv, tv, tnr);
            tL1[v] = 2.f * LOG2E * tv;
        }
        tn21 = tnr * LOG2E;
    } else {
#pragma unroll
        for (int v = 0; v < NV; v++) tL1[v] = 0.f;
    }
    // forward boundary prefill: BIG2 everywhere, except row0 col0 (k==PADB) = 0
    for (int k = tid; k < NBND * W2; k += TPB) bnd1[k] = (k == PADB) ? 0.f : BIG2;
    if (tid == 0) shape_s = 0.f;
    __syncthreads();

    float* gRb = g_R + 32 * (size_t)DS + (size_t)b * ND * DS;

    // ================= forward =================
    {
        float Aprev = BIG2, Aprev2 = BIG2, Bprev = BIG2;
        float upB1 = BIG2, upB2 = BIG2;
        float bndPrev = BIG2;
        float4 po_a = make_float4(0.f, 0.f, 0.f, 0.f);
        float4 po_c = make_float4(0.f, 0.f, 0.f, 0.f);
        const int off = 96 * w;
        const int pstart = 3 * w, pend = 3 * w + 12;
        const float* bRrow = bnd1 + w * W2 + PADB;
        float* bRnext = bnd1 + (w + 1) * W2 + PADB;
        for (int p = 0; p < 28; p++) {
            if (p >= pstart && p <= pend) {
                int S0 = p << 5;
                int jA = S0 - off - 2 * l + 1;
                if (p == pstart) {
                    if (l == 0) bndPrev = bRrow[jA - 1];
                    const float* ojm = opack + (jA - 2 + PADO) * PSTR;  // column jA-1
                    po_a = *(const float4*)ojm;
                    po_c = *(const float4*)(ojm + 4);
                }
                float* gptr = gRb + (size_t)(S0 - off + 64 * w + 2) * DS + (i0 - 1);
                const float* oj = opack + (jA - 1 + PADO) * PSTR;        // column jA
#pragma unroll 8
                for (int k = 0; k < 32; k++) {
                    bool actA = ok0 && ((unsigned)(jA - 1) < (unsigned)NN);
                    bool actB = ok1 && ((unsigned)(jA - 2) < (unsigned)NN);
                    float4 a = *(const float4*)oj;
                    float4 c = *(const float4*)(oj + 4);
                    // D2A: row i0, column jA
                    float dA = tn20 + c.w;
                    dA = fmaf(-tL0[0], a.x, dA);
                    dA = fmaf(-tL0[1], a.y, dA);
                    dA = fmaf(-tL0[2], a.z, dA);
                    dA = fmaf(-tL0[3], a.w, dA);
                    dA = fmaf(-tL0[4], c.x, dA);
                    dA = fmaf(-tL0[5], c.y, dA);
                    dA = fmaf(-tL0[6], c.z, dA);
                    float D2A = fmaxf(dA, 0.f);
                    // D2B: row i1, column jA-1 (previous step's column regs)
                    float dB = tn21 + po_c.w;
                    dB = fmaf(-tL1[0], po_a.x, dB);
                    dB = fmaf(-tL1[1], po_a.y, dB);
                    dB = fmaf(-tL1[2], po_a.z, dB);
                    dB = fmaf(-tL1[3], po_a.w, dB);
                    dB = fmaf(-tL1[4], po_c.x, dB);
                    dB = fmaf(-tL1[5], po_c.y, dB);
                    dB = fmaf(-tL1[6], po_c.z, dB);
                    float D2B = fmaxf(dB, 0.f);
                    // cell A (i0, jA): up/diag from lane l-1's B (prev steps) or smem
                    float rdA = upB2, ruA = upB1;
                    if (l == 0) {
                        float bndCur = bRrow[jA];
                        ruA = bndCur; rdA = bndPrev;
                        bndPrev = bndCur;
                    }
                    float RA = softmin2(rdA, ruA, Aprev) + D2A;
                    RA = actA ? RA : BIG2;
                    // cell B (i1, jA-1): deps all lane-local (A prev steps, B prev)
                    float RB = softmin2(Aprev2, Aprev, Bprev) + D2B;
                    RB = actB ? RB : BIG2;
                    if (actA) gptr[0] = RA;
                    if (actB) {
                        gptr[1] = RB;
                        if (l == 31) bRnext[jA - 1] = RB;
                    }
                    float sh = __shfl_up_sync(FULLM, RB, 1);
                    upB2 = upB1; upB1 = sh;
                    Aprev2 = Aprev; Aprev = RA; Bprev = RB;
                    po_a = a; po_c = c;
                    jA++; gptr += DS; oj += PSTR;
                }
            }
            __syncthreads();
        }
    }

    // re-init boundaries for backward: E = 0, s = NEGS
    for (int k = tid; k < NBND * W2; k += TPB) { bnd1[k] = 0.f; bnd2[k] = NEGS; }
    __syncthreads();

    // ================= backward =================
    float tacc = 0.f;
    {
        float EAp = 0.f, sAp = NEGS;      // A at prev step  -> (i0, jA+1)
        float EBp = 0.f, sBp = NEGS;      // B at prev step  -> (i1, jA) / (i1, jB+1)
        float EBp2 = 0.f, sBp2 = NEGS;    // B two steps ago -> (i1, jA+1)
        float dnE1 = 0.f, dnS1 = NEGS;    // lane l+1 A prev step  -> (i1+1, jB)
        float dnE2 = 0.f, dnS2 = NEGS;    // lane l+1 A 2 steps ago -> (i1+1, jB+1)
        float bndEp = 0.f, bndSp = NEGS;  // lane 31 boundary prev (col jB+1)
        float4 po_a = make_float4(0.f, 0.f, 0.f, 0.f);
        float4 po_c = make_float4(0.f, 0.f, 0.f, 0.f);
        float2 ring[PF];
        const int pstart = 15 - 3 * w;
        const int pend = (878 - 96 * w) >> 5;
        const float* bErow = bnd1 + (w + 1) * W2 + PADB;
        const float* bSrow = bnd2 + (w + 1) * W2 + PADB;
        float* bEw = bnd1 + w * W2 + PADB;
        float* bSw = bnd2 + w * W2 + PADB;
        const bool seed_lane = (i1 == NN);
        for (int p = 0; p < 28; p++) {
            if (p >= pstart && p <= pend) {
                int S0 = p << 5;
                int d0 = 880 - 32 * w - S0;
                int jA = d0 - i0;
                const float* rp = gRb + (size_t)d0 * DS + (i0 - 1);
                if (p == pstart) {
                    const float* q = rp;
#pragma unroll
                    for (int qq = 0; qq < PF; qq++) { ring[qq] = *(const float2*)q; q -= DS; }
                    const float* oji = opack + (jA - 1 + PADO) * PSTR;   // column jA
                    po_a = *(const float4*)oji;
                    po_c = *(const float4*)(oji + 4);
                }
                const float* ppf = rp - (size_t)PF * DS;
                const float* ojb = opack + (jA - 2 + PADO) * PSTR;       // column jB = jA-1
                float dfA = (float)(i0 - jA);
#pragma unroll
                for (int kb = 0; kb < 4; kb++) {
#pragma unroll
                    for (int kk = 0; kk < PF; kk++) {
                        bool actA = ok0 && ((unsigned)(jA - 1) < (unsigned)NN);
                        bool actB = ok1 && ((unsigned)(jA - 2) < (unsigned)NN);
                        float2 Rv = ring[kk];
                        ring[kk] = *(const float2*)ppf; ppf -= DS;
                        float RA = Rv.x, RB = Rv.y;
                        float4 ba = *(const float4*)ojb;
                        float4 bc = *(const float4*)(ojb + 4);
                        // D2A: row i0, column jA (prev regs)
                        float dA = tn20 + po_c.w;
                        dA = fmaf(-tL0[0], po_a.x, dA);
                        dA = fmaf(-tL0[1], po_a.y, dA);
                        dA = fmaf(-tL0[2], po_a.z, dA);
                        dA = fmaf(-tL0[3], po_a.w, dA);
                        dA = fmaf(-tL0[4], po_c.x, dA);
                        dA = fmaf(-tL0[5], po_c.y, dA);
                        dA = fmaf(-tL0[6], po_c.z, dA);
                        float D2A = fmaxf(dA, 0.f);
                        // D2B: row i1, column jB
                        float dB = tn21 + bc.w;
                        dB = fmaf(-tL1[0], ba.x, dB);
                        dB = fmaf(-tL1[1], ba.y, dB);
                        dB = fmaf(-tL1[2], ba.z, dB);
                        dB = fmaf(-tL1[3], ba.w, dB);
                        dB = fmaf(-tL1[4], bc.x, dB);
                        dB = fmaf(-tL1[5], bc.y, dB);
                        dB = fmaf(-tL1[6], bc.z, dB);
                        float D2B = fmaxf(dB, 0.f);
                        // cell A (i0, jA)
                        float wa1 = ex2f(sBp - RA);      // (i1, jA)
                        float wa2 = ex2f(sAp - RA);      // (i0, jA+1)
                        float wa3 = ex2f(sBp2 - RA);     // (i1, jA+1)
                        float EA = fmaf(EBp, wa1, fmaf(EAp, wa2, EBp2 * wa3));
                        float sA = RA - D2A;
                        EA = actA ? EA : 0.f;
                        sA = actA ? sA : NEGS;
                        // cell B (i1, jB)
                        float e1 = dnE1, s1 = dnS1, e2 = dnE2, s2 = dnS2;
                        if (l == 31) {
                            float bEc = bErow[jA - 1];   // col jB
                            float bSc = bSrow[jA - 1];
                            e1 = bEc; s1 = bSc;
                            e2 = bndEp; s2 = bndSp;      // col jB+1 (prev read)
                            bndEp = bEc; bndSp = bSc;
                        }
                        float wb1 = ex2f(s1 - RB);       // (i1+1, jB)
                        float wb2 = ex2f(sBp - RB);      // (i1, jB+1)
                        float wb3 = ex2f(s2 - RB);       // (i1+1, jB+1)
                        float EB = fmaf(e1, wb1, fmaf(EBp, wb2, e2 * wb3));
                        if (seed_lane && (jA - 1) == NN) { EB = 1.f; shape_s = RB * LN2; }
                        float sB = RB - D2B;
                        EB = actB ? EB : 0.f;
                        sB = actB ? sB : NEGS;
                        // temporal sums: dfA = i0-jA, dfB = i1-jB = dfA+2
                        tacc = fmaf(EA, dfA * dfA, tacc);
                        float dfB = dfA + 2.f;
                        tacc = fmaf(EB, dfB * dfB, tacc);
                        // lane 0 exports row i0 = 64w+1 for warp w-1
                        if (actA && l == 0 && w > 0) { bEw[jA] = EA; bSw[jA] = sA; }
                        float shE = __shfl_down_sync(FULLM, EA, 1);
                        float shS = __shfl_down_sync(FULLM, sA, 1);
                        dnE2 = dnE1; dnS2 = dnS1;
                        dnE1 = shE;  dnS1 = shS;
                        EBp2 = EBp;  sBp2 = sBp;
                        EBp = EB;    sBp = sB;
                        EAp = EA;    sAp = sA;
                        po_a = ba;   po_c = bc;
                        jA--; dfA += 1.f; ojb -= PSTR;
                    }
                }
            }
            __syncthreads();
        }
    }

    // ------- reduce temporal accumulator, finalize in last CTA -------
#pragma unroll
    for (int o2 = 16; o2; o2 >>= 1) tacc += __shfl_down_sync(FULLM, tacc, o2);
    if (l == 0) warpsum[w] = tacc;
    __syncthreads();
    if (tid == 0) {
        float sum = 0.f;
#pragma unroll
        for (int q = 0; q < NWARP; q++) sum += warpsum[q];
        atomicAdd(&g_temp_acc, (double)sum);
        atomicAdd(&g_shape_acc, (double)shape_s);
        __threadfence();
        unsigned old = atomicAdd(&g_done, 1u);
        if (old == NB - 1) {
            __threadfence();
            double shape    = g_shape_acc / (double)NB;
            double temporal = g_temp_acc / ((double)NN * NN * NB * NB);
            out[0] = (float)(0.5 * shape + 0.5 * temporal);
            g_shape_acc = 0.0;
            g_temp_acc  = 0.0;
            __threadfence();
            g_done = 0u;
        }
    }
}

extern "C" void kernel_launch(void* const* d_in, const int* in_sizes, int n_in,
                              void* d_out, int out_size) {
    const float* outputs = (const float*)d_in[0];
    const float* targets = (const float*)d_in[1];
    static int smem_set = 0;
    int smem_bytes = (NPTS * PSTR + 2 * NBND * W2) * sizeof(float);   // 57600 B
    if (!smem_set) {
        cudaFuncSetAttribute(dilate_kernel, cudaFuncAttributeMaxDynamicSharedMemorySize,
                             smem_bytes);
        smem_set = 1;
    }
    dilate_kernel<<<NB, TPB, smem_bytes>>>(outputs, targets, (float*)d_out);
}

// round 11
// speedup vs baseline: 1.7004x; 1.0154x over previous
#include <cuda_runtime.h>

// DILATE loss — band-wavefront soft-DTW, one CTA per batch (grid 256).
// R11: forward stores the softmin gradient WEIGHTS (float2 wd,wu per cell;
// wl = 1-wd-wu) instead of R. Backward is then a pure linear recurrence
// E = Pu(i+1,j) + Pl(i,j+1) + Pd(i+1,j+1), P* = E*w* — no MUFU, no D-recompute.
// Forward: warp w rows 32w+1..32w+32, lanes column-staggered, shfl deps,
// smem boundary rows (64-col skew), barrier per 32 steps, base-2 math.

#define NB    256
#define NN    336
#define NV    7
#define ND    673
#define DS    352
#define TPB   352
#define NW    11
#define W2    512
#define PADJ  64
#define PSTR  12
#define NPTS  (NN + 2*PADJ)
#define LOG2E 1.4426950408889634f
#define LN2   0.6931471805599453f
#define BIG2  1.442695e8f
#define PF    16
#define FULLM 0xffffffffu

// weights, diagonal-major; 32 diag front pad + 64 back pad (pads stay zero)
__device__ float2   g_W[((size_t)NB * ND + 96) * DS];
__device__ double   g_shape_acc;
__device__ double   g_temp_acc;
__device__ unsigned g_done;

static __device__ __forceinline__ float ex2f(float x) {
    float r; asm("ex2.approx.f32 %0, %1;" : "=f"(r) : "f"(x)); return r;
}
static __device__ __forceinline__ float lg2f(float x) {
    float r; asm("lg2.approx.f32 %0, %1;" : "=f"(r) : "f"(x)); return r;
}
static __device__ __forceinline__ float rcpf(float x) {
    float r; asm("rcp.approx.f32 %0, %1;" : "=f"(r) : "f"(x)); return r;
}

extern __shared__ float smem[];

__global__ __launch_bounds__(TPB, 2)
void dilate_kernel(const float* __restrict__ outputs,
                   const float* __restrict__ targets,
                   float* __restrict__ out) {
    const int b   = blockIdx.x;
    const int tid = threadIdx.x;
    const int w   = tid >> 5;
    const int l   = tid & 31;
    const int i   = 32 * w + l + 1;
    const bool row_ok = (i <= NN);

    float* opack = smem;                     // [NPTS][PSTR]: 0-6 dims, 7 = log2e*||o||^2
    float* bnd1  = opack + NPTS * PSTR;      // fwd: R boundary; bwd: Pu boundary [NW][W2]
    float* bnd2  = bnd1 + NW * W2;           // bwd: Pd boundary
    __shared__ float warpsum[NW];
    __shared__ float shape_s;

    const float* ob = outputs + (size_t)b * NN * NV;
    const float* tb = targets + (size_t)b * NN * NV;

    // pack output points (zero-padded)
    for (int k = tid; k < NPTS * PSTR; k += TPB) opack[k] = 0.f;
    __syncthreads();
    for (int k = tid; k < NN * NV; k += TPB) {
        int j = k / NV, v = k - j * NV;
        opack[(j + PADJ) * PSTR + v] = ob[k];
    }
    __syncthreads();
    for (int j = tid; j < NN; j += TPB) {
        float s = 0.f;
#pragma unroll
        for (int v = 0; v < NV; v++) { float x = opack[(j + PADJ) * PSTR + v]; s = fmaf(x, x, s); }
        opack[(j + PADJ) * PSTR + 7] = s * LOG2E;
    }
    float tL[NV], tn2 = 0.f;
    if (row_ok) {
        float tnr = 0.f;
#pragma unroll
        for (int v = 0; v < NV; v++) {
            float tv = tb[(i - 1) * NV + v];
            tnr = fmaf(tv, tv, tnr);
            tL[v] = 2.f * LOG2E * tv;
        }
        tn2 = tnr * LOG2E;
    } else {
#pragma unroll
        for (int v = 0; v < NV; v++) tL[v] = 0.f;
    }
    // forward boundary prefill: BIG2 everywhere except R[0][0]=0 (race-free fill)
    for (int k = tid; k < NW * W2; k += TPB) bnd1[k] = (k == PADJ) ? 0.f : BIG2;
    if (tid == 0) shape_s = 0.f;
    __syncthreads();

    float2* gWb = g_W + 32 * (size_t)DS + (size_t)b * ND * DS;
    const bool nn_lane = (i == NN);

    // ================= forward =================
    {
        float Rprev = BIG2, upc = BIG2, upp = BIG2, prevB = BIG2;
        const int off = 64 * w;
        const int pstart = off >> 5, pend = (off + 366) >> 5;
        const float* bArow = bnd1 + w * W2 + PADJ;
        float* bAnext = bnd1 + (w + 1) * W2 + PADJ;
        for (int p = 0; p < 31; p++) {
            if (p >= pstart && p <= pend) {
                int s0 = p << 5;
                int j = s0 - off - l + 1;
                if (p == pstart && l == 0) prevB = bArow[0];
                float2* gptr = gWb + (size_t)(s0 - 32 * w + 2) * DS + i;
                const float* oj = opack + (j - 1 + PADJ) * PSTR;
#pragma unroll 8
                for (int k = 0; k < 32; k++) {
                    bool act = row_ok && ((unsigned)(j - 1) < (unsigned)NN);
                    const float4 a = *(const float4*)(oj);
                    const float4 c = *(const float4*)(oj + 4);
                    float acc0 = tn2 + c.w;
                    acc0 = fmaf(-tL[0], a.x, acc0);
                    acc0 = fmaf(-tL[1], a.y, acc0);
                    acc0 = fmaf(-tL[2], a.z, acc0);
                    acc0 = fmaf(-tL[3], a.w, acc0);
                    acc0 = fmaf(-tL[4], c.x, acc0);
                    acc0 = fmaf(-tL[5], c.y, acc0);
                    acc0 = fmaf(-tL[6], c.z, acc0);
                    float D2 = fmaxf(acc0, 0.f);
                    float ru = upc, rd = upp, curB = 0.f;
                    if (l == 0) { curB = bArow[j]; ru = curB; rd = prevB; }
                    float rl = Rprev;
                    float m  = fminf(fminf(rd, ru), rl);
                    float ed = ex2f(m - rd);
                    float eu = ex2f(m - ru);
                    float el = ex2f(m - rl);
                    float z  = ed + eu + el;
                    float Rn = D2 + m - lg2f(z);
                    float rz = rcpf(z);
                    Rn = act ? Rn : BIG2;
                    if (act) {
                        *gptr = make_float2(ed * rz, eu * rz);
                        if (l == 31 && w < NW - 1) bAnext[j] = Rn;
                        if (nn_lane && j == NN) shape_s = Rn * LN2;
                    }
                    float sh = __shfl_up_sync(FULLM, Rn, 1);
                    upp = upc; upc = sh;
                    if (l == 0) prevB = curB;
                    Rprev = Rn;
                    j++; gptr += DS; oj += PSTR;
                }
            }
            __syncthreads();
        }
    }

    // re-init boundaries for backward: products = 0
    for (int k = tid; k < NW * W2; k += TPB) { bnd1[k] = 0.f; bnd2[k] = 0.f; }
    __syncthreads();

    // ================= backward (pure linear recurrence) =================
    float tacc = 0.f;
    {
        float Plp  = 0.f;                 // own Pl from prev step -> (i, j+1)
        float PuD1 = 0.f, PdD1 = 0.f;     // lane l+1, prev step
        float PdD2 = 0.f;                 // lane l+1, two steps ago
        float2 ring[PF];
        const int off = 64 * (10 - w);
        const int pstart = off >> 5, pend = (off + 366) >> 5;
        const float* b1row = bnd1 + w * W2 + PADJ;
        const float* b2row = bnd2 + w * W2 + PADJ;
        float* b1prev = bnd1 + (w - 1) * W2 + PADJ;
        float* b2prev = bnd2 + (w - 1) * W2 + PADJ;
        for (int p = 0; p < 32; p++) {
            if (p >= pstart && p <= pend) {
                int s0 = p << 5;
                if (p == pstart) {
                    const float2* pr = gWb + (size_t)(1008 - 32 * w - s0) * DS + i;
#pragma unroll
                    for (int q = 0; q < PF; q++) { ring[q] = *pr; pr -= DS; }
                }
                int j = 367 + off - s0 - l;
                float df = (float)(i - j);
                const float2* ppf = gWb + (size_t)(1008 - 32 * w - s0 - PF) * DS + i;
#pragma unroll 2
                for (int kb = 0; kb < 2; kb++) {
#pragma unroll
                    for (int kk = 0; kk < PF; kk++) {
                        bool act = row_ok && ((unsigned)(j - 1) < (unsigned)NN);
                        float2 Wv = ring[kk];
                        ring[kk] = *ppf; ppf -= DS;
                        if (l == 31) { PuD1 = b1row[j]; PdD1 = b2row[j]; }
                        float En = PuD1 + Plp + PdD2;
                        if (nn_lane && j == NN) En = 1.f;
                        En = act ? En : 0.f;
                        float wl = 1.f - Wv.x - Wv.y;
                        float Pd = En * Wv.x;
                        float Pu = En * Wv.y;
                        float Pl = En * wl;
                        tacc = fmaf(En, df * df, tacc);
                        if (act && l == 0 && w > 0) { b1prev[j] = Pu; b2prev[j] = Pd; }
                        float sPu = __shfl_down_sync(FULLM, Pu, 1);
                        float sPd = __shfl_down_sync(FULLM, Pd, 1);
                        PdD2 = PdD1;
                        PuD1 = sPu; PdD1 = sPd;
                        Plp = Pl;
                        j--; df += 1.f;
                    }
                }
            }
            __syncthreads();
        }
    }

    // ------- reduce temporal accumulator, finalize in last CTA -------
#pragma unroll
    for (int o2 = 16; o2; o2 >>= 1) tacc += __shfl_down_sync(FULLM, tacc, o2);
    if (l == 0) warpsum[w] = tacc;
    __syncthreads();
    if (tid == 0) {
        float sum = 0.f;
#pragma unroll
        for (int q = 0; q < NW; q++) sum += warpsum[q];
        atomicAdd(&g_temp_acc, (double)sum);
        atomicAdd(&g_shape_acc, (double)shape_s);
        __threadfence();
        unsigned old = atomicAdd(&g_done, 1u);
        if (old == NB - 1) {
            __threadfence();
            double shape    = g_shape_acc / (double)NB;
            double temporal = g_temp_acc / ((double)NN * NN * NB * NB);
            out[0] = (float)(0.5 * shape + 0.5 * temporal);
            g_shape_acc = 0.0;
            g_temp_acc  = 0.0;
            __threadfence();
            g_done = 0u;
        }
    }
}

extern "C" void kernel_launch(void* const* d_in, const int* in_sizes, int n_in,
                              void* d_out, int out_size) {
    const float* outputs = (const float*)d_in[0];
    const float* targets = (const float*)d_in[1];
    static int smem_set = 0;
    int smem_bytes = (NPTS * PSTR + 2 * NW * W2) * sizeof(float);
    if (!smem_set) {
        cudaFuncSetAttribute(dilate_kernel, cudaFuncAttributeMaxDynamicSharedMemorySize,
                             smem_bytes);
        smem_set = 1;
    }
    dilate_kernel<<<NB, TPB, smem_bytes>>>(outputs, targets, (float*)d_out);
}

// round 12
// speedup vs baseline: 1.7112x; 1.0063x over previous
#include <cuda_runtime.h>

// DILATE loss — band-wavefront soft-DTW, one CTA per batch (grid 256).
// R11: forward stores the softmin gradient WEIGHTS (float2 wd,wu per cell;
// wl = 1-wd-wu) instead of R. Backward is then a pure linear recurrence
// E = Pu(i+1,j) + Pl(i,j+1) + Pd(i+1,j+1), P* = E*w* — no MUFU, no D-recompute.
// Forward: warp w rows 32w+1..32w+32, lanes column-staggered, shfl deps,
// smem boundary rows (64-col skew), barrier per 32 steps, base-2 math.

#define NB    256
#define NN    336
#define NV    7
#define ND    673
#define DS    352
#define TPB   352
#define NW    11
#define W2    512
#define PADJ  64
#define PSTR  12
#define NPTS  (NN + 2*PADJ)
#define LOG2E 1.4426950408889634f
#define LN2   0.6931471805599453f
#define BIG2  1.442695e8f
#define PF    16
#define FULLM 0xffffffffu

// weights, diagonal-major; 32 diag front pad + 64 back pad (pads stay zero)
__device__ float2   g_W[((size_t)NB * ND + 96) * DS];
__device__ double   g_shape_acc;
__device__ double   g_temp_acc;
__device__ unsigned g_done;

static __device__ __forceinline__ float ex2f(float x) {
    float r; asm("ex2.approx.f32 %0, %1;" : "=f"(r) : "f"(x)); return r;
}
static __device__ __forceinline__ float lg2f(float x) {
    float r; asm("lg2.approx.f32 %0, %1;" : "=f"(r) : "f"(x)); return r;
}
static __device__ __forceinline__ float rcpf(float x) {
    float r; asm("rcp.approx.f32 %0, %1;" : "=f"(r) : "f"(x)); return r;
}

extern __shared__ float smem[];

__global__ __launch_bounds__(TPB, 2)
void dilate_kernel(const float* __restrict__ outputs,
                   const float* __restrict__ targets,
                   float* __restrict__ out) {
    const int b   = blockIdx.x;
    const int tid = threadIdx.x;
    const int w   = tid >> 5;
    const int l   = tid & 31;
    const int i   = 32 * w + l + 1;
    const bool row_ok = (i <= NN);

    float* opack = smem;                     // [NPTS][PSTR]: 0-6 dims, 7 = log2e*||o||^2
    float* bnd1  = opack + NPTS * PSTR;      // fwd: R boundary; bwd: Pu boundary [NW][W2]
    float* bnd2  = bnd1 + NW * W2;           // bwd: Pd boundary
    __shared__ float warpsum[NW];
    __shared__ float shape_s;

    const float* ob = outputs + (size_t)b * NN * NV;
    const float* tb = targets + (size_t)b * NN * NV;

    // pack output points (zero-padded)
    for (int k = tid; k < NPTS * PSTR; k += TPB) opack[k] = 0.f;
    __syncthreads();
    for (int k = tid; k < NN * NV; k += TPB) {
        int j = k / NV, v = k - j * NV;
        opack[(j + PADJ) * PSTR + v] = ob[k];
    }
    __syncthreads();
    for (int j = tid; j < NN; j += TPB) {
        float s = 0.f;
#pragma unroll
        for (int v = 0; v < NV; v++) { float x = opack[(j + PADJ) * PSTR + v]; s = fmaf(x, x, s); }
        opack[(j + PADJ) * PSTR + 7] = s * LOG2E;
    }
    float tL[NV], tn2 = 0.f;
    if (row_ok) {
        float tnr = 0.f;
#pragma unroll
        for (int v = 0; v < NV; v++) {
            float tv = tb[(i - 1) * NV + v];
            tnr = fmaf(tv, tv, tnr);
            tL[v] = 2.f * LOG2E * tv;
        }
        tn2 = tnr * LOG2E;
    } else {
#pragma unroll
        for (int v = 0; v < NV; v++) tL[v] = 0.f;
    }
    // forward boundary prefill: BIG2 everywhere except R[0][0]=0 (race-free fill)
    for (int k = tid; k < NW * W2; k += TPB) bnd1[k] = (k == PADJ) ? 0.f : BIG2;
    if (tid == 0) shape_s = 0.f;
    __syncthreads();

    float2* gWb = g_W + 32 * (size_t)DS + (size_t)b * ND * DS;
    const bool nn_lane = (i == NN);

    // ================= forward =================
    {
        float Rprev = BIG2, upc = BIG2, upp = BIG2, prevB = BIG2;
        const int off = 64 * w;
        const int pstart = off >> 5, pend = (off + 366) >> 5;
        const float* bArow = bnd1 + w * W2 + PADJ;
        float* bAnext = bnd1 + (w + 1) * W2 + PADJ;
        for (int p = 0; p < 31; p++) {
            if (p >= pstart && p <= pend) {
                int s0 = p << 5;
                int j = s0 - off - l + 1;
                if (p == pstart && l == 0) prevB = bArow[0];
                float2* gptr = gWb + (size_t)(s0 - 32 * w + 2) * DS + i;
                const float* oj = opack + (j - 1 + PADJ) * PSTR;
#pragma unroll 8
                for (int k = 0; k < 32; k++) {
                    bool act = row_ok && ((unsigned)(j - 1) < (unsigned)NN);
                    const float4 a = *(const float4*)(oj);
                    const float4 c = *(const float4*)(oj + 4);
                    float acc0 = tn2 + c.w;
                    acc0 = fmaf(-tL[0], a.x, acc0);
                    acc0 = fmaf(-tL[1], a.y, acc0);
                    acc0 = fmaf(-tL[2], a.z, acc0);
                    acc0 = fmaf(-tL[3], a.w, acc0);
                    acc0 = fmaf(-tL[4], c.x, acc0);
                    acc0 = fmaf(-tL[5], c.y, acc0);
                    acc0 = fmaf(-tL[6], c.z, acc0);
                    float D2 = fmaxf(acc0, 0.f);
                    float ru = upc, rd = upp, curB = 0.f;
                    if (l == 0) { curB = bArow[j]; ru = curB; rd = prevB; }
                    float rl = Rprev;
                    float m  = fminf(fminf(rd, ru), rl);
                    float ed = ex2f(m - rd);
                    float eu = ex2f(m - ru);
                    float el = ex2f(m - rl);
                    float z  = ed + eu + el;
                    float Rn = D2 + m - lg2f(z);
                    float rz = rcpf(z);
                    Rn = act ? Rn : BIG2;
                    if (act) {
                        *gptr = make_float2(ed * rz, eu * rz);
                        if (l == 31 && w < NW - 1) bAnext[j] = Rn;
                        if (nn_lane && j == NN) shape_s = Rn * LN2;
                    }
                    float sh = __shfl_up_sync(FULLM, Rn, 1);
                    upp = upc; upc = sh;
                    if (l == 0) prevB = curB;
                    Rprev = Rn;
                    j++; gptr += DS; oj += PSTR;
                }
            }
            __syncthreads();
        }
    }

    // re-init boundaries for backward: products = 0
    for (int k = tid; k < NW * W2; k += TPB) { bnd1[k] = 0.f; bnd2[k] = 0.f; }
    __syncthreads();

    // ================= backward (pure linear recurrence) =================
    float tacc = 0.f;
    {
        float Plp  = 0.f;                 // own Pl from prev step -> (i, j+1)
        float PuD1 = 0.f, PdD1 = 0.f;     // lane l+1, prev step
        float PdD2 = 0.f;                 // lane l+1, two steps ago
        float2 ring[PF];
        const int off = 64 * (10 - w);
        const int pstart = off >> 5, pend = (off + 366) >> 5;
        const float* b1row = bnd1 + w * W2 + PADJ;
        const float* b2row = bnd2 + w * W2 + PADJ;
        float* b1prev = bnd1 + (w - 1) * W2 + PADJ;
        float* b2prev = bnd2 + (w - 1) * W2 + PADJ;
        for (int p = 0; p < 32; p++) {
            if (p >= pstart && p <= pend) {
                int s0 = p << 5;
                if (p == pstart) {
                    const float2* pr = gWb + (size_t)(1008 - 32 * w - s0) * DS + i;
#pragma unroll
                    for (int q = 0; q < PF; q++) { ring[q] = *pr; pr -= DS; }
                }
                int j = 367 + off - s0 - l;
                float df = (float)(i - j);
                const float2* ppf = gWb + (size_t)(1008 - 32 * w - s0 - PF) * DS + i;
#pragma unroll 2
                for (int kb = 0; kb < 2; kb++) {
#pragma unroll
                    for (int kk = 0; kk < PF; kk++) {
                        bool act = row_ok && ((unsigned)(j - 1) < (unsigned)NN);
                        float2 Wv = ring[kk];
                        ring[kk] = *ppf; ppf -= DS;
                        if (l == 31) { PuD1 = b1row[j]; PdD1 = b2row[j]; }
                        float En = PuD1 + Plp + PdD2;
                        if (nn_lane && j == NN) En = 1.f;
                        En = act ? En : 0.f;
                        float wl = 1.f - Wv.x - Wv.y;
                        float Pd = En * Wv.x;
                        float Pu = En * Wv.y;
                        float Pl = En * wl;
                        tacc = fmaf(En, df * df, tacc);
                        if (act && l == 0 && w > 0) { b1prev[j] = Pu; b2prev[j] = Pd; }
                        float sPu = __shfl_down_sync(FULLM, Pu, 1);
                        float sPd = __shfl_down_sync(FULLM, Pd, 1);
                        PdD2 = PdD1;
                        PuD1 = sPu; PdD1 = sPd;
                        Plp = Pl;
                        j--; df += 1.f;
                    }
                }
            }
            __syncthreads();
        }
    }

    // ------- reduce temporal accumulator, finalize in last CTA -------
#pragma unroll
    for (int o2 = 16; o2; o2 >>= 1) tacc += __shfl_down_sync(FULLM, tacc, o2);
    if (l == 0) warpsum[w] = tacc;
    __syncthreads();
    if (tid == 0) {
        float sum = 0.f;
#pragma unroll
        for (int q = 0; q < NW; q++) sum += warpsum[q];
        atomicAdd(&g_temp_acc, (double)sum);
        atomicAdd(&g_shape_acc, (double)shape_s);
        __threadfence();
        unsigned old = atomicAdd(&g_done, 1u);
        if (old == NB - 1) {
            __threadfence();
            double shape    = g_shape_acc / (double)NB;
            double temporal = g_temp_acc / ((double)NN * NN * NB * NB);
            out[0] = (float)(0.5 * shape + 0.5 * temporal);
            g_shape_acc = 0.0;
            g_temp_acc  = 0.0;
            __threadfence();
            g_done = 0u;
        }
    }
}

extern "C" void kernel_launch(void* const* d_in, const int* in_sizes, int n_in,
                              void* d_out, int out_size) {
    const float* outputs = (const float*)d_in[0];
    const float* targets = (const float*)d_in[1];
    static int smem_set = 0;
    int smem_bytes = (NPTS * PSTR + 2 * NW * W2) * sizeof(float);
    if (!smem_set) {
        cudaFuncSetAttribute(dilate_kernel, cudaFuncAttributeMaxDynamicSharedMemorySize,
                             smem_bytes);
        smem_set = 1;
    }
    dilate_kernel<<<NB, TPB, smem_bytes>>>(outputs, targets, (float*)d_out);
}